// round 8
// baseline (speedup 1.0000x reference)
#include <cuda_runtime.h>
#include <stdint.h>

#define NN 100000
#define EE 3200000
#define TT 8
#define FF 64
#define NK (NN * TT)            // 800000 sort buckets (dst*8 + t)
#define SCAN_BLKS (NK / 256)    // 3125

// ---------------- device scratch (allocation-free) ----------------
__device__ float g_h1[(size_t)NN * FF];   // 25.6 MB
__device__ int   g_sedge[EE];             // src, sorted by (dst*8+t)
__device__ int   g_kcnt[NK];
__device__ int   g_off[NK + 1];
__device__ int   g_kcur[NK];
__device__ int   g_bsum[SCAN_BLKS + 3];
__device__ int   g_mode;                  // 1 = int64 indices, 0 = int32

#define FMA2(acc, a, b) asm("fma.rn.f32x2 %0, %1, %2, %0;" : "+l"(acc) : "l"(a), "l"(b))
__device__ __forceinline__ unsigned long long dup2(float v) {
    unsigned long long r;
    unsigned int b = __float_as_uint(v);
    asm("mov.b64 %0, {%1, %1};" : "=l"(r) : "r"(b));
    return r;
}
__device__ __forceinline__ unsigned long long pack2(float lo, float hi) {
    unsigned long long r;
    asm("mov.b64 %0, {%1, %2};" : "=l"(r) : "r"(__float_as_uint(lo)), "r"(__float_as_uint(hi)));
    return r;
}
__device__ __forceinline__ float2 unpack2(unsigned long long v) {
    unsigned int lo, hi;
    asm("mov.b64 {%0, %1}, %2;" : "=r"(lo), "=r"(hi) : "l"(v));
    return make_float2(__uint_as_float(lo), __uint_as_float(hi));
}

// ---------------- dtype detection ----------------
__global__ void k_detect(const int* __restrict__ ei) {
    __shared__ int any_nonzero;
    if (threadIdx.x == 0) any_nonzero = 0;
    __syncthreads();
    int v = ei[2 * threadIdx.x + 1];
    if (v != 0) atomicExch(&any_nonzero, 1);
    __syncthreads();
    if (threadIdx.x == 0) g_mode = (any_nonzero == 0) ? 1 : 0;
}

__global__ void k_zero_k(void) {
    int i = blockIdx.x * 256 + threadIdx.x;
    if (i < NK) g_kcnt[i] = 0;
}

__device__ __forceinline__ void decode_edge(const void* ei_raw, const void* ti_raw,
                                            int e, int& src, int& dst, int& t) {
    if (g_mode) {
        const long long* ei = (const long long*)ei_raw;
        const long long* ti = (const long long*)ti_raw;
        src = (int)ei[e];
        dst = (int)ei[(size_t)EE + e];
        t   = (int)ti[e];
    } else {
        const int* ei = (const int*)ei_raw;
        const int* ti = (const int*)ti_raw;
        src = ei[e];
        dst = ei[EE + e];
        t   = ti[e];
    }
}

// ---------------- histogram over key = dst*8 + t ----------------
__global__ void k_hist(const void* __restrict__ ei_raw, const void* __restrict__ ti_raw) {
    int e = blockIdx.x * 256 + threadIdx.x;
    if (e >= EE) return;
    int src, dst, t;
    decode_edge(ei_raw, ti_raw, e, src, dst, t);
    atomicAdd(&g_kcnt[dst * TT + t], 1);
}

// ---------------- hierarchical scan: stage 1 (block scans) ----------------
__global__ void __launch_bounds__(256) k_scan1(void) {
    __shared__ int sh[256];
    int i = blockIdx.x * 256 + threadIdx.x;
    int v = g_kcnt[i];
    sh[threadIdx.x] = v;
    __syncthreads();
#pragma unroll
    for (int off = 1; off < 256; off <<= 1) {
        int u = 0;
        if (threadIdx.x >= off) u = sh[threadIdx.x - off];
        __syncthreads();
        if (threadIdx.x >= off) sh[threadIdx.x] += u;
        __syncthreads();
    }
    g_off[i] = sh[threadIdx.x] - v;           // exclusive within block
    if (threadIdx.x == 255) g_bsum[blockIdx.x] = sh[255];
}

// ---------------- stage 2: scan the 3125 block totals ----------------
__global__ void __launch_bounds__(1024) k_scan2(void) {
    __shared__ int ps[1024];
    int tid = threadIdx.x;
    int base = tid * 4;
    int vals[4];
    int s = 0;
#pragma unroll
    for (int k = 0; k < 4; k++) {
        int idx = base + k;
        vals[k] = (idx < SCAN_BLKS) ? g_bsum[idx] : 0;
        s += vals[k];
    }
    ps[tid] = s;
    __syncthreads();
    for (int off = 1; off < 1024; off <<= 1) {
        int u = 0;
        if (tid >= off) u = ps[tid - off];
        __syncthreads();
        if (tid >= off) ps[tid] += u;
        __syncthreads();
    }
    int run = ps[tid] - s;                    // exclusive start of this chunk
#pragma unroll
    for (int k = 0; k < 4; k++) {
        int idx = base + k;
        if (idx < SCAN_BLKS) g_bsum[idx] = run;
        run += vals[k];
    }
}

// ---------------- stage 3: add block offsets ----------------
__global__ void __launch_bounds__(256) k_scan3(void) {
    int i = blockIdx.x * 256 + threadIdx.x;
    int v = g_off[i] + g_bsum[blockIdx.x];
    g_off[i] = v;
    g_kcur[i] = v;
    if (i == 0) g_off[NK] = EE;
}

// ---------------- permute: g_sedge sorted by (dst*8+t) ----------------
__global__ void k_permute(const void* __restrict__ ei_raw, const void* __restrict__ ti_raw) {
    int e = blockIdx.x * 256 + threadIdx.x;
    if (e >= EE) return;
    int src, dst, t;
    decode_edge(ei_raw, ti_raw, e, src, dst, t);
    int pos = atomicAdd(&g_kcur[dst * TT + t], 1);
    g_sedge[pos] = src;
}

// ---------------- fused: CSR aggregate (registers) + GEMM + bias + relu ----
// 256 thr = 8 warps; half-warp per dst (16 dsts/block).
// Phase A: per (dst,t) bucket accumulate float4 in registers, store to smem.
// Phase B: [16,512] @ [512,64] with f32x2 FMAs, fused bias+relu.
__global__ void __launch_bounds__(256) k_fused(const float* __restrict__ in,
                                               const float* __restrict__ W,
                                               const float* __restrict__ bias,
                                               float* __restrict__ out) {
    __shared__ float xs[16][520];
    int tid = threadIdx.x;
    int warpid = tid >> 5, lane = tid & 31;
    int nb = blockIdx.x * 16;

    // ---- Phase A ----
    {
        int eh = lane >> 4;                // half-warp id
        int li = lane & 15;                // float4 column 0..15
        int slot = warpid * 2 + eh;        // 0..15
        int d = nb + slot;
        int base = d * TT;
        const float4* x4 = (const float4*)in;
        int s = __ldg(&g_off[base]);
#pragma unroll
        for (int t = 0; t < TT; t++) {
            int en = __ldg(&g_off[base + t + 1]);
            float4 acc = make_float4(0.f, 0.f, 0.f, 0.f);
            for (int e = s; e < en; e++) {
                int src = __ldg(&g_sedge[e]);
                float4 v = __ldg(&x4[(size_t)src * 16 + li]);
                acc.x += v.x; acc.y += v.y; acc.z += v.z; acc.w += v.w;
            }
            *(float4*)&xs[slot][t * 64 + li * 4] = acc;
            s = en;
        }
    }
    __syncthreads();

    // ---- Phase B ----
    int row = tid >> 4;                    // 0..15
    int fo4 = tid & 15;                    // float4 output column
    const float4* W4 = (const float4*)W;   // [512][16]

    unsigned long long a0 = 0, a1 = 0;
#pragma unroll 4
    for (int f4 = 0; f4 < 128; f4++) {
        float4 xv = *(const float4*)&xs[row][f4 * 4];
        float4 w0 = __ldg(&W4[(f4 * 4 + 0) * 16 + fo4]);
        float4 w1 = __ldg(&W4[(f4 * 4 + 1) * 16 + fo4]);
        float4 w2 = __ldg(&W4[(f4 * 4 + 2) * 16 + fo4]);
        float4 w3 = __ldg(&W4[(f4 * 4 + 3) * 16 + fo4]);
        unsigned long long x0 = dup2(xv.x), x1 = dup2(xv.y);
        unsigned long long x2 = dup2(xv.z), x3 = dup2(xv.w);
        FMA2(a0, x0, pack2(w0.x, w0.y)); FMA2(a1, x0, pack2(w0.z, w0.w));
        FMA2(a0, x1, pack2(w1.x, w1.y)); FMA2(a1, x1, pack2(w1.z, w1.w));
        FMA2(a0, x2, pack2(w2.x, w2.y)); FMA2(a1, x2, pack2(w2.z, w2.w));
        FMA2(a0, x3, pack2(w3.x, w3.y)); FMA2(a1, x3, pack2(w3.z, w3.w));
    }

    float4 bv = __ldg(&((const float4*)bias)[fo4]);
    float2 lo = unpack2(a0), hi = unpack2(a1);
    float4 r;
    r.x = fmaxf(lo.x + bv.x, 0.f);
    r.y = fmaxf(lo.y + bv.y, 0.f);
    r.z = fmaxf(hi.x + bv.z, 0.f);
    r.w = fmaxf(hi.y + bv.w, 0.f);
    ((float4*)out)[(size_t)(nb + row) * 16 + fo4] = r;
}

// ---------------- ssl = h2 @ Wssl + bssl ----------------
__global__ void __launch_bounds__(256) k_ssl(const float* __restrict__ h2,
                                             const float* __restrict__ Wssl,
                                             const float* __restrict__ bssl,
                                             float* __restrict__ out) {
    __shared__ float ws[64 * 64];
    __shared__ float hs[4 * 64];
    int tid = threadIdx.x;
    int nb  = blockIdx.x * 4;

    {
        float4* wsv = (float4*)ws;
        const float4* Wv = (const float4*)Wssl;
#pragma unroll
        for (int k = 0; k < 4; k++) wsv[tid + k * 256] = Wv[tid + k * 256];
        hs[tid] = h2[(size_t)nb * 64 + tid];
    }
    __syncthreads();

    int nl = tid >> 6;
    int fo = tid & 63;
    float a = __ldg(&bssl[fo]);
#pragma unroll 8
    for (int fin = 0; fin < 64; ++fin)
        a += hs[nl * 64 + fin] * ws[fin * 64 + fo];
    out[(size_t)(nb + nl) * 64 + fo] = a;
}

// ---------------- launch ----------------
extern "C" void kernel_launch(void* const* d_in, const int* in_sizes, int n_in,
                              void* d_out, int out_size) {
    const float* x    = (const float*)d_in[0];
    const void*  ei   = d_in[1];
    const void*  ti   = d_in[2];
    const float* W1   = (const float*)d_in[3];
    const float* b1   = (const float*)d_in[4];
    const float* W2   = (const float*)d_in[5];
    const float* b2   = (const float*)d_in[6];
    const float* Wssl = (const float*)d_in[7];
    const float* bssl = (const float*)d_in[8];
    float* out_h   = (float*)d_out;
    float* out_ssl = (float*)d_out + (size_t)NN * 64;

    float* dh1;  cudaGetSymbolAddress((void**)&dh1, g_h1);

    // counting sort by (dst*8 + t), hierarchical scan
    k_detect<<<1, 256>>>((const int*)ei);
    k_zero_k<<<SCAN_BLKS, 256>>>();
    k_hist<<<EE / 256, 256>>>(ei, ti);
    k_scan1<<<SCAN_BLKS, 256>>>();
    k_scan2<<<1, 1024>>>();
    k_scan3<<<SCAN_BLKS, 256>>>();
    k_permute<<<EE / 256, 256>>>(ei, ti);

    // fused layers (no atomics, no intermediate y)
    k_fused<<<NN / 16, 256>>>(x, W1, b1, dh1);
    k_fused<<<NN / 16, 256>>>(dh1, W2, b2, out_h);

    // ssl head
    k_ssl<<<NN / 4, 256>>>(out_h, Wssl, bssl, out_ssl);
}